// round 10
// baseline (speedup 1.0000x reference)
#include <cuda_runtime.h>
#include <cuda_fp16.h>

#define NV     101          // tokens incl. start symbol (start = 100)
#define UMX    256
#define NSTEPS 257
#define G3     3072
#define NCTA   128
#define NTHR   512

typedef unsigned u32;

// ---------------- static device scratch (no runtime allocation) ----------------
// Fragment-packed fp16 hi/lo weights.
// g_W0p: phase A (K=1024): n-rows 0..3071 = W_hh layer0 (r,z,n), 3072..4095 = lin_W.
//   [ntile(512)][ktile(64)][lane(32)] : uint4 = {Whi.b0, Whi.b1, Wlo.b0, Wlo.b1}
__device__ __align__(16) uint4 g_W0p[512 * 64 * 32];            // 16 MB
// g_W12p: layers 1,2 (K=2048): per layer n-row q*1024+j:
//   q=0:[Wih_r|Whh_r] q=1:[Wih_z|Whh_z] q=2:[Wih_n|0] q=3:[0|Whh_n]
//   [layer(2)][ntile(512)][ktile(128)][lane(32)]
__device__ __align__(16) uint4 g_W12p[2 * 512 * 128 * 32];      // 64 MB
// Fragment-packed fp16 activations (single plane): [l(3)][par(2)][mtile(4)][ktile(128)][lane(32)]
//   l=0: cols 0..1023 = h0; l=1,2: cols 0..1023 = x, 1024..2047 = h_prev
__device__ __align__(16) uint4 g_A[3 * 2 * 4 * 128 * 32];       // 1.5 MB
__device__ float g_T[NV * G3];          // layer0 gi table (incl b_ih0), fp32
__device__ float g_stf[3 * 64 * 1024];  // fp32 states [l][b][j]
__device__ unsigned g_bar;

// ---------------- grid barrier: release-arrive + acquire-poll (no MEMBAR) ----------------
__device__ __forceinline__ void gridbar() {
    __syncthreads();
    if (threadIdx.x == 0) {
        u32 ticket;
        asm volatile("atom.add.release.gpu.global.u32 %0, [%1], 1;"
                     : "=r"(ticket) : "l"(&g_bar) : "memory");
        u32 target = ((ticket + NCTA) / NCTA) * NCTA;   // round (ticket+1) up to mult of NCTA
        u32 cur;
        do {
            asm volatile("ld.acquire.gpu.global.u32 %0, [%1];"
                         : "=r"(cur) : "l"(&g_bar) : "memory");
        } while (cur < target);
    }
    __syncthreads();
}

__device__ __forceinline__ float sigm(float t) { return 1.0f / (1.0f + expf(-t)); }

// split fp32 -> (hi, lo) fp16 bit patterns
__device__ __forceinline__ void sph(float w, u32& hb, u32& lb) {
    __half h = __float2half_rn(w);
    hb = (u32)__half_as_ushort(h);
    lb = (u32)__half_as_ushort(__float2half_rn(w - __half2float(h)));
}
__device__ __forceinline__ uint4 pack4h(float a, float b, float c, float d) {
    u32 ah, al, bh, bl, ch, cl, dh, dl;
    sph(a, ah, al); sph(b, bh, bl); sph(c, ch, cl); sph(d, dh, dl);
    uint4 v;
    v.x = ah | (bh << 16);   // hi b0 (k0, k0+1)
    v.y = ch | (dh << 16);   // hi b1 (k0+8, k0+9)
    v.z = al | (bl << 16);   // lo b0
    v.w = cl | (dl << 16);   // lo b1
    return v;
}

// A-buffer offset (uint4 units, excluding lane)
__device__ __forceinline__ size_t aoff(int l, int par, int mt, int kt) {
    return (size_t)((((l * 2 + par) * 4 + mt) * 128 + kt)) * 32;
}
// Write activation element (b, c) as fp16 into fragment layout
__device__ __forceinline__ void storeA(int l, int par, int b, int c, float v) {
    int mt = b >> 4, mr = b & 15, kt = c >> 4, kk = c & 15;
    int lane = (mr & 7) * 4 + ((kk & 7) >> 1);
    int slot = (mr >> 3) + ((kk >> 3) << 1);
    __half* p = (__half*)(g_A + aoff(l, par, mt, kt) + lane);
    p[slot * 2 + (kk & 1)] = __float2half_rn(v);
}

// ---------------- mma.m16n8k16 fp16 ----------------
__device__ __forceinline__ void mma_f16(float* d, const uint4& a, u32 b0, u32 b1) {
    asm volatile(
        "mma.sync.aligned.m16n8k16.row.col.f32.f16.f16.f32 "
        "{%0,%1,%2,%3}, {%4,%5,%6,%7}, {%8,%9}, {%0,%1,%2,%3};"
        : "+f"(d[0]), "+f"(d[1]), "+f"(d[2]), "+f"(d[3])
        : "r"(a.x), "r"(a.y), "r"(a.z), "r"(a.w), "r"(b0), "r"(b1));
}
// 2-chain combine + store 16x8 tile into smem slab (float[128])
__device__ __forceinline__ void stD2(float* base, int rr, int cc,
                                     const float* d0, const float* d1) {
    base[rr * 8 + cc]           = d0[0] + d1[0];
    base[rr * 8 + cc + 1]       = d0[1] + d1[1];
    base[(rr + 8) * 8 + cc]     = d0[2] + d1[2];
    base[(rr + 8) * 8 + cc + 1] = d0[3] + d1[3];
}

// ================================================================================
__global__ void __launch_bounds__(NTHR, 1)
decoder_kernel(const int*   __restrict__ y,
               const float* __restrict__ embed,
               const float* __restrict__ W_ih,
               const float* __restrict__ W_hh,
               const float* __restrict__ b_ih,
               const float* __restrict__ b_hh,
               const float* __restrict__ init_state,
               const float* __restrict__ lin_W,
               const float* __restrict__ lin_b,
               float*       __restrict__ out)
{
    const int tid  = threadIdx.x;
    const int lane = tid & 31;
    const int wid  = tid >> 5;          // 0..15
    const int mwA  = wid & 3;           // phase A: m-tile
    const int ksA  = wid >> 2;          // phase A: k-slice 0..3 (16 ktiles each)
    const int mpB  = wid & 1;           // B/C: m-half (mtiles {0,1} or {2,3})
    const int ksB  = wid >> 1;          // B/C: k-slice 0..7 (16 ktiles each)
    const int cta  = blockIdx.x;
    const int gt   = cta * NTHR + tid;
    const int GS   = NCTA * NTHR;
    const int rr   = lane >> 2, cc = (lane & 3) << 1;

    __shared__ float sbuf[12288];       // exactly 48 KB reduction buffer
    // phase A view: [s(4)][mt(4)][q(4)][128]
    #define SA(s, mt, q) (sbuf + (((s) * 4 + (mt)) * 4 + (q)) * 128)
    // B/C view: [s(8)][mt(4)][g(3)][128]; g=2 holds i_n for s<4, h_n for s>=4
    #define SB(s, mt, g) (sbuf + (((s) * 4 + (mt)) * 3 + (g)) * 128)

    // ================= PROLOGUE =================
    for (int idx = gt; idx < 512 * 64 * 32; idx += GS) {
        int ln = idx & 31, t = (idx >> 5) & 63, NT = idx >> 11;
        int n  = NT * 8 + (ln >> 2);
        int k0 = t * 16 + ((ln & 3) << 1);
        const float* src = (n < 3072) ? (W_hh + (size_t)n * 1024)
                                      : (lin_W + (size_t)(n - 3072) * 1024);
        g_W0p[idx] = pack4h(src[k0], src[k0 + 1], src[k0 + 8], src[k0 + 9]);
    }
    for (int idx = gt; idx < 2 * 512 * 128 * 32; idx += GS) {
        int ln = idx & 31, t = (idx >> 5) & 127, NT = (idx >> 12) & 511, ll = idx >> 21;
        int n  = NT * 8 + (ln >> 2);
        int qq = n >> 10, jj = n & 1023;
        int k0 = t * 16 + ((ln & 3) << 1);
        int lay = ll + 1;
        float w[4];
#pragma unroll
        for (int i = 0; i < 4; ++i) {
            int k = k0 + ((i >> 1) << 3) + (i & 1);   // k0, k0+1, k0+8, k0+9
            float v = 0.0f;
            if (qq < 2) {
                v = (k < 1024) ? W_ih[((size_t)lay * 3072 + qq * 1024 + jj) * 1024 + k]
                               : W_hh[((size_t)lay * 3072 + qq * 1024 + jj) * 1024 + k - 1024];
            } else if (qq == 2) {
                if (k < 1024) v = W_ih[((size_t)lay * 3072 + 2048 + jj) * 1024 + k];
            } else {
                if (k >= 1024) v = W_hh[((size_t)lay * 3072 + 2048 + jj) * 1024 + k - 1024];
            }
            w[i] = v;
        }
        g_W12p[idx] = pack4h(w[0], w[1], w[2], w[3]);
    }
    // fp32 token table: T[v][row] = embed[v] . W_ih0[row] + b_ih0[row]
    for (int idx = gt; idx < 3072 * 128; idx += GS) {
        int row = idx >> 7, v = idx & 127;
        if (v < NV) {
            const float* e = embed + (size_t)v * 1024;
            const float* w = W_ih + (size_t)row * 1024;
            float a0 = 0, a1 = 0, a2 = 0, a3 = 0;
            for (int k = 0; k < 1024; k += 4) {
                a0 += e[k] * w[k];         a1 += e[k + 1] * w[k + 1];
                a2 += e[k + 2] * w[k + 2]; a3 += e[k + 3] * w[k + 3];
            }
            g_T[v * G3 + row] = (a0 + a1) + (a2 + a3) + b_ih[row];
        }
    }
    for (int idx = gt; idx < 3 * 64 * 1024; idx += GS) {
        int l = idx >> 16, r = idx & 65535, b = r >> 10, j = r & 1023;
        float v = init_state[l * 1024 + j];
        g_stf[idx] = v;
        storeA(l, 0, b, (l == 0) ? j : (1024 + j), v);
    }
    gridbar();

    // ================= STEP LOOP =================
    for (int u = 0; u < NSTEPS; ++u) {
        const int par = u & 1;

        // ----- phase A: layer0 h-GEMM (r,z,n on h0) + lin of u-1 (on h2), K=1024 -----
        {
            const int t0 = ksA * 16;
            const uint4* A0 = g_A + aoff(0, par, mwA, t0) + lane;
            const uint4* A2 = g_A + aoff(2, par, mwA, 64 + t0) + lane;
            const uint4* B0 = g_W0p + ((size_t)(0 * 128 + cta) * 64 + t0) * 32 + lane;
            const uint4* B1 = g_W0p + ((size_t)(1 * 128 + cta) * 64 + t0) * 32 + lane;
            const uint4* B2 = g_W0p + ((size_t)(2 * 128 + cta) * 64 + t0) * 32 + lane;
            const uint4* B3 = g_W0p + ((size_t)(3 * 128 + cta) * 64 + t0) * 32 + lane;
            float d0a[4] = {}, d0b[4] = {}, d1a[4] = {}, d1b[4] = {};
            float d2a[4] = {}, d2b[4] = {}, d3a[4] = {}, d3b[4] = {};
            uint4 b0 = B0[0], b1 = B1[0], b2 = B2[0], b3 = B3[0];
#pragma unroll 1
            for (int i = 0; i < 15; ++i) {
                uint4 b0n = B0[(i + 1) * 32], b1n = B1[(i + 1) * 32];
                uint4 b2n = B2[(i + 1) * 32], b3n = B3[(i + 1) * 32];
                uint4 a = A0[i * 32], c = A2[i * 32];
                mma_f16(d0a, a, b0.x, b0.y); mma_f16(d0b, a, b0.z, b0.w);
                mma_f16(d1a, a, b1.x, b1.y); mma_f16(d1b, a, b1.z, b1.w);
                mma_f16(d2a, a, b2.x, b2.y); mma_f16(d2b, a, b2.z, b2.w);
                mma_f16(d3a, c, b3.x, b3.y); mma_f16(d3b, c, b3.z, b3.w);
                b0 = b0n; b1 = b1n; b2 = b2n; b3 = b3n;
            }
            {
                uint4 a = A0[15 * 32], c = A2[15 * 32];
                mma_f16(d0a, a, b0.x, b0.y); mma_f16(d0b, a, b0.z, b0.w);
                mma_f16(d1a, a, b1.x, b1.y); mma_f16(d1b, a, b1.z, b1.w);
                mma_f16(d2a, a, b2.x, b2.y); mma_f16(d2b, a, b2.z, b2.w);
                mma_f16(d3a, c, b3.x, b3.y); mma_f16(d3b, c, b3.z, b3.w);
            }
            stD2(SA(ksA, mwA, 0), rr, cc, d0a, d0b);
            stD2(SA(ksA, mwA, 1), rr, cc, d1a, d1b);
            stD2(SA(ksA, mwA, 2), rr, cc, d2a, d2b);
            stD2(SA(ksA, mwA, 3), rr, cc, d3a, d3b);
        }
        __syncthreads();
        {   // epilogue A: GRU layer0 + out[u-1]
            int b = tid >> 3, jj = tid & 7, mm = b >> 4, r2 = b & 15;
            float Dr = 0, Dz = 0, Dn = 0, Do = 0;
#pragma unroll
            for (int s = 0; s < 4; ++s) {
                Dr += SA(s, mm, 0)[r2 * 8 + jj];
                Dz += SA(s, mm, 1)[r2 * 8 + jj];
                Dn += SA(s, mm, 2)[r2 * 8 + jj];
                Do += SA(s, mm, 3)[r2 * 8 + jj];
            }
            int jcol = cta * 8 + jj;
            int tok = (u == 0) ? (NV - 1) : y[b * UMX + (u - 1)];
            const float* Tv = g_T + (size_t)tok * G3;
            float r = sigm(Tv[jcol] + Dr + b_hh[jcol]);
            float z = sigm(Tv[1024 + jcol] + Dz + b_hh[1024 + jcol]);
            float n = tanhf(Tv[2048 + jcol] + r * (Dn + b_hh[2048 + jcol]));
            float hp = g_stf[b * 1024 + jcol];
            float h = (1.0f - z) * n + z * hp;
            g_stf[b * 1024 + jcol] = h;
            storeA(1, par, b, jcol, h);          // x for layer1 this step
            storeA(0, par ^ 1, b, jcol, h);      // h0 for next step
            if (u > 0)
                out[(size_t)b * NSTEPS * 1024 + (size_t)(u - 1) * 1024 + jcol] = Do + lin_b[jcol];
        }
        gridbar();

        // ----- phases B, C: layers 1, 2 (K=2048; warp = (m-half, k-slice of 8)) -----
#pragma unroll 1
        for (int l = 1; l <= 2; ++l) {
            {
                const int t0  = ksB * 16;
                const int g2q = 2 + (ksB >> 2);        // i_n for ks<4, h_n for ks>=4
                const int mt0 = mpB * 2;
                const uint4* A  = g_A + aoff(l, par, mt0, t0) + lane;
                const uint4* B0 = g_W12p + ((size_t)((l - 1) * 512 + 0 * 128 + cta) * 128 + t0) * 32 + lane;
                const uint4* B1 = g_W12p + ((size_t)((l - 1) * 512 + 1 * 128 + cta) * 128 + t0) * 32 + lane;
                const uint4* B2 = g_W12p + ((size_t)((l - 1) * 512 + g2q * 128 + cta) * 128 + t0) * 32 + lane;
                float m0g0a[4] = {}, m0g0b[4] = {}, m0g1a[4] = {}, m0g1b[4] = {};
                float m0g2a[4] = {}, m0g2b[4] = {};
                float m1g0a[4] = {}, m1g0b[4] = {}, m1g1a[4] = {}, m1g1b[4] = {};
                float m1g2a[4] = {}, m1g2b[4] = {};
                uint4 b0 = B0[0], b1 = B1[0], b2 = B2[0];
#pragma unroll 1
                for (int i = 0; i < 15; ++i) {
                    uint4 b0n = B0[(i + 1) * 32], b1n = B1[(i + 1) * 32], b2n = B2[(i + 1) * 32];
                    uint4 a0 = A[i * 32], a1 = A[i * 32 + 128 * 32];
                    mma_f16(m0g0a, a0, b0.x, b0.y); mma_f16(m0g0b, a0, b0.z, b0.w);
                    mma_f16(m0g1a, a0, b1.x, b1.y); mma_f16(m0g1b, a0, b1.z, b1.w);
                    mma_f16(m0g2a, a0, b2.x, b2.y); mma_f16(m0g2b, a0, b2.z, b2.w);
                    mma_f16(m1g0a, a1, b0.x, b0.y); mma_f16(m1g0b, a1, b0.z, b0.w);
                    mma_f16(m1g1a, a1, b1.x, b1.y); mma_f16(m1g1b, a1, b1.z, b1.w);
                    mma_f16(m1g2a, a1, b2.x, b2.y); mma_f16(m1g2b, a1, b2.z, b2.w);
                    b0 = b0n; b1 = b1n; b2 = b2n;
                }
                {
                    uint4 a0 = A[15 * 32], a1 = A[15 * 32 + 128 * 32];
                    mma_f16(m0g0a, a0, b0.x, b0.y); mma_f16(m0g0b, a0, b0.z, b0.w);
                    mma_f16(m0g1a, a0, b1.x, b1.y); mma_f16(m0g1b, a0, b1.z, b1.w);
                    mma_f16(m0g2a, a0, b2.x, b2.y); mma_f16(m0g2b, a0, b2.z, b2.w);
                    mma_f16(m1g0a, a1, b0.x, b0.y); mma_f16(m1g0b, a1, b0.z, b0.w);
                    mma_f16(m1g1a, a1, b1.x, b1.y); mma_f16(m1g1b, a1, b1.z, b1.w);
                    mma_f16(m1g2a, a1, b2.x, b2.y); mma_f16(m1g2b, a1, b2.z, b2.w);
                }
                stD2(SB(ksB, mt0, 0), rr, cc, m0g0a, m0g0b);
                stD2(SB(ksB, mt0, 1), rr, cc, m0g1a, m0g1b);
                stD2(SB(ksB, mt0, 2), rr, cc, m0g2a, m0g2b);
                stD2(SB(ksB, mt0 + 1, 0), rr, cc, m1g0a, m1g0b);
                stD2(SB(ksB, mt0 + 1, 1), rr, cc, m1g1a, m1g1b);
                stD2(SB(ksB, mt0 + 1, 2), rr, cc, m1g2a, m1g2b);
            }
            __syncthreads();
            {   // epilogue: GRU layer l
                int b = tid >> 3, jj = tid & 7, mm = b >> 4, r2 = b & 15;
                float Gr = 0, Gz = 0, Gi = 0, Gh = 0;
#pragma unroll
                for (int s = 0; s < 8; ++s) {
                    Gr += SB(s, mm, 0)[r2 * 8 + jj];
                    Gz += SB(s, mm, 1)[r2 * 8 + jj];
                }
#pragma unroll
                for (int s = 0; s < 4; ++s) Gi += SB(s, mm, 2)[r2 * 8 + jj];
#pragma unroll
                for (int s = 4; s < 8; ++s) Gh += SB(s, mm, 2)[r2 * 8 + jj];
                int jcol = cta * 8 + jj;
                const float* bi  = b_ih + l * G3;
                const float* bhv = b_hh + l * G3;
                float r = sigm(Gr + bi[jcol] + bhv[jcol]);
                float z = sigm(Gz + bi[1024 + jcol] + bhv[1024 + jcol]);
                float n = tanhf(Gi + bi[2048 + jcol] + r * (Gh + bhv[2048 + jcol]));
                float hp = g_stf[(l * 64 + b) * 1024 + jcol];
                float h = (1.0f - z) * n + z * hp;
                g_stf[(l * 64 + b) * 1024 + jcol] = h;
                if (l == 1) {
                    storeA(2, par, b, jcol, h);              // x for layer2 this step
                    storeA(1, par ^ 1, b, 1024 + jcol, h);   // h1 next step
                } else {
                    storeA(2, par ^ 1, b, 1024 + jcol, h);   // h2: lin + layer2 next step
                }
            }
            gridbar();
        }
    }

    // ================= FINAL OUTPUT (u = NSTEPS-1) =================
    {
        const int t0 = ksA * 16;
        const uint4* A2 = g_A + aoff(2, NSTEPS & 1, mwA, 64 + t0) + lane;
        const uint4* B3 = g_W0p + ((size_t)(384 + cta) * 64 + t0) * 32 + lane;
        float da[4] = {}, db[4] = {};
#pragma unroll 2
        for (int i = 0; i < 16; ++i) {
            uint4 c = A2[i * 32], b3 = B3[i * 32];
            mma_f16(da, c, b3.x, b3.y);
            mma_f16(db, c, b3.z, b3.w);
        }
        stD2(SA(ksA, mwA, 0), rr, cc, da, db);
    }
    __syncthreads();
    {
        int b = tid >> 3, jj = tid & 7, mm = b >> 4, r2 = b & 15;
        float Do = 0;
#pragma unroll
        for (int s = 0; s < 4; ++s) Do += SA(s, mm, 0)[r2 * 8 + jj];
        int jcol = cta * 8 + jj;
        out[(size_t)b * NSTEPS * 1024 + (size_t)(NSTEPS - 1) * 1024 + jcol] = Do + lin_b[jcol];
    }
    #undef SA
    #undef SB
}

extern "C" void kernel_launch(void* const* d_in, const int* in_sizes, int n_in,
                              void* d_out, int out_size) {
    (void)in_sizes; (void)n_in; (void)out_size;
    const int*   y          = (const int*)  d_in[0];
    // d_in[1] = U (unused by the reference math)
    const float* embed      = (const float*)d_in[2];
    const float* W_ih       = (const float*)d_in[3];
    const float* W_hh       = (const float*)d_in[4];
    const float* b_ih       = (const float*)d_in[5];
    const float* b_hh       = (const float*)d_in[6];
    const float* init_state = (const float*)d_in[7];
    const float* lin_W      = (const float*)d_in[8];
    const float* lin_b      = (const float*)d_in[9];
    float* out = (float*)d_out;

    decoder_kernel<<<NCTA, NTHR>>>(y, embed, W_ih, W_hh, b_ih, b_hh,
                                   init_state, lin_W, lin_b, out);
}